// round 1
// baseline (speedup 1.0000x reference)
#include <cuda_runtime.h>
#include <math.h>

// Problem constants (fixed shapes from metadata)
#define T_TOK 4096          // B*S = 2*2048
#define D_DIM 1024
#define E_NUM 8
#define W_DIM 1024
#define SLOTS (T_TOK * 2)   // top-2 -> exactly 2 slots per token

// ---------------- device scratch (static globals; no allocation) -----------
__device__ int   g_count[E_NUM];
__device__ int   g_fill [E_NUM];
__device__ int   g_off  [E_NUM + 1];
__device__ int   g_sel  [T_TOK * 2];
__device__ float g_selw [T_TOK * 2];
__device__ int   g_tok  [SLOTS];
__device__ float g_wt   [SLOTS];
__device__ float g_act  [(size_t)SLOTS * W_DIM];   // ~33.5 MB activation buffer

// ---------------- K0: zero output + counters -------------------------------
__global__ void zero_kernel(float* __restrict__ out) {
    int i = blockIdx.x * blockDim.x + threadIdx.x;
    if (i < T_TOK * D_DIM) out[i] = 0.0f;
    if (i < E_NUM) { g_count[i] = 0; g_fill[i] = 0; }
}

// ---------------- K1: router (one warp per token) --------------------------
__global__ void router_kernel(const float* __restrict__ x,
                              const float* __restrict__ rw) {
    int warp = (blockIdx.x * blockDim.x + threadIdx.x) >> 5;
    int lane = threadIdx.x & 31;
    if (warp >= T_TOK) return;
    const float* xr = x + (size_t)warp * D_DIM;

    float p[E_NUM];
#pragma unroll
    for (int e = 0; e < E_NUM; e++) p[e] = 0.0f;

    for (int d = lane; d < D_DIM; d += 32) {
        float xv = xr[d];
#pragma unroll
        for (int e = 0; e < E_NUM; e++) p[e] += xv * rw[e * D_DIM + d];
    }
#pragma unroll
    for (int e = 0; e < E_NUM; e++) {
#pragma unroll
        for (int o = 16; o; o >>= 1) p[e] += __shfl_xor_sync(0xffffffffu, p[e], o);
    }
    if (lane == 0) {
        // top-2 of logits (sigmoid monotonic); ties -> lowest index (jax top_k)
        int i1 = 0; float v1 = p[0];
#pragma unroll
        for (int e = 1; e < E_NUM; e++) if (p[e] > v1) { v1 = p[e]; i1 = e; }
        int i2 = -1; float v2 = -3.0e38f;
#pragma unroll
        for (int e = 0; e < E_NUM; e++) if (e != i1 && p[e] > v2) { v2 = p[e]; i2 = e; }

        float p1 = 1.0f / (1.0f + expf(-v1));
        float p2 = 1.0f / (1.0f + expf(-v2));
        float s  = p1 + p2 + 1e-20f;
        g_sel [warp * 2 + 0] = i1;  g_sel [warp * 2 + 1] = i2;
        g_selw[warp * 2 + 0] = p1 / s;
        g_selw[warp * 2 + 1] = p2 / s;
        atomicAdd(&g_count[i1], 1);
        atomicAdd(&g_count[i2], 1);
    }
}

// ---------------- K2: exclusive prefix over 8 counts -----------------------
__global__ void offsets_kernel() {
    if (threadIdx.x == 0 && blockIdx.x == 0) {
        int s = 0;
#pragma unroll
        for (int e = 0; e < E_NUM; e++) { g_off[e] = s; s += g_count[e]; }
        g_off[E_NUM] = s;
    }
}

// ---------------- K3: fill per-expert slot lists ---------------------------
__global__ void fill_kernel() {
    int t = blockIdx.x * blockDim.x + threadIdx.x;
    if (t >= T_TOK) return;
#pragma unroll
    for (int k = 0; k < 2; k++) {
        int e   = g_sel[t * 2 + k];
        int pos = g_off[e] + atomicAdd(&g_fill[e], 1);
        g_tok[pos] = t;
        g_wt [pos] = g_selw[t * 2 + k];
    }
}

// ---------------- grouped GEMMs --------------------------------------------
#define BM 128
#define BN 128
#define BK 8

// Up-proj: h = x[tok] @ W1e ; act = wt * relu(h)^2
__global__ __launch_bounds__(256, 2)
void up_gemm(const float* __restrict__ x, const float* __restrict__ w1) {
    int e   = blockIdx.z;
    int cnt = g_count[e];
    int m0  = blockIdx.y * BM;
    if (m0 >= cnt) return;
    int n0   = blockIdx.x * BN;
    int base = g_off[e];

    __shared__ float As[BK][BM + 4];
    __shared__ float Bs[BK][BN + 4];

    int tid = threadIdx.x;
    int tx  = tid & 15, ty = tid >> 4;

    // A load assignment: row am (0..127), k-chunk ac (0 or 4)
    int am = tid >> 1;
    int ac = (tid & 1) * 4;
    int aslot = base + m0 + am; if (aslot > SLOTS - 1) aslot = SLOTS - 1;
    const float* arow = x + (size_t)g_tok[aslot] * D_DIM;

    // B load assignment: k-row br (0..7), n-chunk bc
    int br = tid >> 5;
    int bc = (tid & 31) * 4;
    const float* bptr = w1 + (size_t)e * W_DIM + n0;   // B[k][n] = bptr[k*E*W + n]

    float acc[8][8];
#pragma unroll
    for (int i = 0; i < 8; i++)
#pragma unroll
        for (int j = 0; j < 8; j++) acc[i][j] = 0.0f;

    for (int k0 = 0; k0 < D_DIM; k0 += BK) {
        float4 av = *(const float4*)(arow + k0 + ac);
        float4 bv = *(const float4*)(bptr + (size_t)(k0 + br) * (E_NUM * W_DIM) + bc);
        __syncthreads();
        As[ac + 0][am] = av.x; As[ac + 1][am] = av.y;
        As[ac + 2][am] = av.z; As[ac + 3][am] = av.w;
        *(float4*)&Bs[br][bc] = bv;
        __syncthreads();
#pragma unroll
        for (int kk = 0; kk < BK; kk++) {
            float ra[8], rb[8];
#pragma unroll
            for (int i = 0; i < 8; i++) ra[i] = As[kk][ty * 8 + i];
#pragma unroll
            for (int j = 0; j < 8; j++) rb[j] = Bs[kk][tx * 8 + j];
#pragma unroll
            for (int i = 0; i < 8; i++)
#pragma unroll
                for (int j = 0; j < 8; j++)
                    acc[i][j] = fmaf(ra[i], rb[j], acc[i][j]);
        }
    }

#pragma unroll
    for (int i = 0; i < 8; i++) {
        int m = m0 + ty * 8 + i;
        if (m < cnt) {
            int slot = base + m;
            float wt = g_wt[slot];
            float* orow = g_act + (size_t)slot * W_DIM + n0 + tx * 8;
            float v[8];
#pragma unroll
            for (int j = 0; j < 8; j++) {
                float h = acc[i][j];
                v[j] = (h > 0.0f) ? h * h * wt : 0.0f;
            }
            *(float4*)(orow + 0) = make_float4(v[0], v[1], v[2], v[3]);
            *(float4*)(orow + 4) = make_float4(v[4], v[5], v[6], v[7]);
        }
    }
}

// Down-proj: out[tok] += act[slot] @ W2e   (atomicAdd combine, 2 adds/elem)
__global__ __launch_bounds__(256, 2)
void down_gemm(const float* __restrict__ w2, float* __restrict__ out) {
    int e   = blockIdx.z;
    int cnt = g_count[e];
    int m0  = blockIdx.y * BM;
    if (m0 >= cnt) return;
    int n0   = blockIdx.x * BN;
    int base = g_off[e];

    __shared__ float As[BK][BM + 4];
    __shared__ float Bs[BK][BN + 4];

    int tid = threadIdx.x;
    int tx  = tid & 15, ty = tid >> 4;

    int am = tid >> 1;
    int ac = (tid & 1) * 4;
    int aslot = base + m0 + am; if (aslot > SLOTS - 1) aslot = SLOTS - 1;
    const float* arow = g_act + (size_t)aslot * W_DIM;

    int br = tid >> 5;
    int bc = (tid & 31) * 4;
    const float* bptr = w2 + (size_t)e * W_DIM * D_DIM + n0;  // B[k][n] = bptr[k*D + n]

    float acc[8][8];
#pragma unroll
    for (int i = 0; i < 8; i++)
#pragma unroll
        for (int j = 0; j < 8; j++) acc[i][j] = 0.0f;

    for (int k0 = 0; k0 < W_DIM; k0 += BK) {
        float4 av = *(const float4*)(arow + k0 + ac);
        float4 bv = *(const float4*)(bptr + (size_t)(k0 + br) * D_DIM + bc);
        __syncthreads();
        As[ac + 0][am] = av.x; As[ac + 1][am] = av.y;
        As[ac + 2][am] = av.z; As[ac + 3][am] = av.w;
        *(float4*)&Bs[br][bc] = bv;
        __syncthreads();
#pragma unroll
        for (int kk = 0; kk < BK; kk++) {
            float ra[8], rb[8];
#pragma unroll
            for (int i = 0; i < 8; i++) ra[i] = As[kk][ty * 8 + i];
#pragma unroll
            for (int j = 0; j < 8; j++) rb[j] = Bs[kk][tx * 8 + j];
#pragma unroll
            for (int i = 0; i < 8; i++)
#pragma unroll
                for (int j = 0; j < 8; j++)
                    acc[i][j] = fmaf(ra[i], rb[j], acc[i][j]);
        }
    }

#pragma unroll
    for (int i = 0; i < 8; i++) {
        int m = m0 + ty * 8 + i;
        if (m < cnt) {
            int tok = g_tok[base + m];
            float* orow = out + (size_t)tok * D_DIM + n0 + tx * 8;
#pragma unroll
            for (int j = 0; j < 8; j++) atomicAdd(&orow[j], acc[i][j]);
        }
    }
}

// ---------------- launch ----------------------------------------------------
extern "C" void kernel_launch(void* const* d_in, const int* in_sizes, int n_in,
                              void* d_out, int out_size) {
    const float* x  = (const float*)d_in[0];   // [2,2048,1024]
    const float* rw = (const float*)d_in[1];   // [8,1024]
    const float* w1 = (const float*)d_in[2];   // [1024, 8192]
    const float* w2 = (const float*)d_in[3];   // [8192, 1024]
    float* out = (float*)d_out;                // [2,2048,1024]

    zero_kernel<<<(T_TOK * D_DIM + 255) / 256, 256>>>(out);
    router_kernel<<<(T_TOK * 32 + 255) / 256, 256>>>(x, rw);
    offsets_kernel<<<1, 32>>>();
    fill_kernel<<<(T_TOK + 255) / 256, 256>>>();

    // grids: N-tiles=W/BN=8, M-tiles worst case T/BM=32, experts=8
    dim3 ggrid(W_DIM / BN, T_TOK / BM, E_NUM);
    up_gemm<<<ggrid, 256>>>(x, w1);
    dim3 dgrid(D_DIM / BN, T_TOK / BM, E_NUM);
    down_gemm<<<dgrid, 256>>>(w2, out);
}

// round 3
// speedup vs baseline: 1.5495x; 1.5495x over previous
#include <cuda_runtime.h>
#include <cuda_bf16.h>
#include <math.h>
#include <stdint.h>

// ---------------- problem constants ----------------------------------------
#define T_TOK 4096
#define D_DIM 1024
#define E_NUM 8
#define W_DIM 1024
#define SLOTS 8192          // T*2 (top-2)
#define K3    3072          // concatenated K: A=[hi|hi|lo], B=[hi|lo|hi]
#define BK    32
#define NCH   (K3 / BK)     // 96
#define SAS   40            // smem row stride (bf16) -> conflict-free frag LDS

// ---------------- device scratch --------------------------------------------
__device__ int   g_count[E_NUM];
__device__ int   g_fill [E_NUM];
__device__ int   g_off  [E_NUM + 1];
__device__ int   g_sel  [T_TOK * 2];
__device__ float g_selw [T_TOK * 2];
__device__ int   g_tok  [SLOTS];
__device__ float g_wt   [SLOTS];
__device__ __nv_bfloat16 g_xcat [(size_t)T_TOK * K3];          // 25 MB
__device__ __nv_bfloat16 g_w1cat[(size_t)E_NUM * W_DIM * K3];  // 50 MB [e][n][k]
__device__ __nv_bfloat16 g_w2cat[(size_t)E_NUM * D_DIM * K3];  // 50 MB [e][d][k]
__device__ __nv_bfloat16 g_acat [(size_t)SLOTS * K3];          // 50 MB [slot][k]

// ---------------- small kernels ---------------------------------------------
__global__ void zero_kernel(float* __restrict__ out) {
    int i = blockIdx.x * blockDim.x + threadIdx.x;
    if (i < T_TOK * D_DIM) out[i] = 0.0f;
    if (i < E_NUM) { g_count[i] = 0; g_fill[i] = 0; }
}

__global__ void router_kernel(const float* __restrict__ x, const float* __restrict__ rw) {
    int warp = (blockIdx.x * blockDim.x + threadIdx.x) >> 5;
    int lane = threadIdx.x & 31;
    if (warp >= T_TOK) return;
    const float* xr = x + (size_t)warp * D_DIM;
    float p[E_NUM];
#pragma unroll
    for (int e = 0; e < E_NUM; e++) p[e] = 0.0f;
    for (int d = lane; d < D_DIM; d += 32) {
        float xv = xr[d];
#pragma unroll
        for (int e = 0; e < E_NUM; e++) p[e] += xv * rw[e * D_DIM + d];
    }
#pragma unroll
    for (int e = 0; e < E_NUM; e++)
#pragma unroll
        for (int o = 16; o; o >>= 1) p[e] += __shfl_xor_sync(0xffffffffu, p[e], o);
    if (lane == 0) {
        int i1 = 0; float v1 = p[0];
#pragma unroll
        for (int e = 1; e < E_NUM; e++) if (p[e] > v1) { v1 = p[e]; i1 = e; }
        int i2 = -1; float v2 = -3.0e38f;
#pragma unroll
        for (int e = 0; e < E_NUM; e++) if (e != i1 && p[e] > v2) { v2 = p[e]; i2 = e; }
        float p1 = 1.0f / (1.0f + expf(-v1));
        float p2 = 1.0f / (1.0f + expf(-v2));
        float s = p1 + p2 + 1e-20f;
        g_sel [warp * 2 + 0] = i1;  g_sel [warp * 2 + 1] = i2;
        g_selw[warp * 2 + 0] = p1 / s;
        g_selw[warp * 2 + 1] = p2 / s;
        atomicAdd(&g_count[i1], 1);
        atomicAdd(&g_count[i2], 1);
    }
}

__global__ void offsets_kernel() {
    if (threadIdx.x == 0 && blockIdx.x == 0) {
        int s = 0;
#pragma unroll
        for (int e = 0; e < E_NUM; e++) { g_off[e] = s; s += g_count[e]; }
        g_off[E_NUM] = s;
    }
}

__global__ void fill_kernel() {
    int t = blockIdx.x * blockDim.x + threadIdx.x;
    if (t >= T_TOK) return;
#pragma unroll
    for (int k = 0; k < 2; k++) {
        int e = g_sel[t * 2 + k];
        int pos = g_off[e] + atomicAdd(&g_fill[e], 1);
        g_tok[pos] = t;
        g_wt [pos] = g_selw[t * 2 + k];
    }
}

// x -> [hi | hi | lo] bf16, row-major [T][3072]
__global__ void convert_x(const float* __restrict__ x) {
    int i = blockIdx.x * blockDim.x + threadIdx.x;
    if (i >= T_TOK * D_DIM) return;
    int t = i >> 10, d = i & 1023;
    float v = x[i];
    __nv_bfloat16 hi = __float2bfloat16(v);
    __nv_bfloat16 lo = __float2bfloat16(v - __bfloat162float(hi));
    size_t b = (size_t)t * K3;
    g_xcat[b + d] = hi; g_xcat[b + 1024 + d] = hi; g_xcat[b + 2048 + d] = lo;
}

// Per-expert 1024x1024 transpose + split: dst[e][n][k-seg], segs [hi|lo|hi]
// sel: 0 -> w1 (src_ld=8192, col offset e*1024), 1 -> w2 (src_ld=1024, row offset e*1024)
__global__ void convert_w(const float* __restrict__ src, int sel) {
    __shared__ float tile[32][33];
    int e = blockIdx.z;
    int r0 = blockIdx.y * 32, c0 = blockIdx.x * 32;
    int src_ld  = sel ? 1024 : 8192;
    int row_off = sel ? e * 1024 : 0;
    int col_off = sel ? 0 : e * 1024;
    const float* s = src + (size_t)(row_off + r0) * src_ld + col_off + c0;
#pragma unroll
    for (int i = threadIdx.y; i < 32; i += 8)
        tile[i][threadIdx.x] = s[(size_t)i * src_ld + threadIdx.x];
    __syncthreads();
    __nv_bfloat16* d = (sel ? g_w2cat : g_w1cat) + (size_t)e * 1024 * K3;
#pragma unroll
    for (int i = threadIdx.y; i < 32; i += 8) {
        int c = c0 + i;               // dst row (N index)
        int r = r0 + threadIdx.x;     // dst col (K index)
        float v = tile[threadIdx.x][i];
        __nv_bfloat16 hi = __float2bfloat16(v);
        __nv_bfloat16 lo = __float2bfloat16(v - __bfloat162float(hi));
        size_t bi = (size_t)c * K3 + r;
        d[bi] = hi; d[bi + 1024] = lo; d[bi + 2048] = hi;
    }
}

// ---------------- mma.sync helper -------------------------------------------
__device__ __forceinline__ void mma16816(float* d, const uint32_t* a, const uint32_t* b) {
    asm volatile(
        "mma.sync.aligned.m16n8k16.row.col.f32.bf16.bf16.f32 "
        "{%0,%1,%2,%3}, {%4,%5,%6,%7}, {%8,%9}, {%0,%1,%2,%3};"
        : "+f"(d[0]), "+f"(d[1]), "+f"(d[2]), "+f"(d[3])
        : "r"(a[0]), "r"(a[1]), "r"(a[2]), "r"(a[3]), "r"(b[0]), "r"(b[1]));
}

// ---------------- grouped GEMM (HMMA via mma.sync, bf16x3) -------------------
// MODE 0: up-proj  (A = g_xcat gathered by token, B = g_w1cat, epi -> g_acat split)
// MODE 1: down-proj(A = g_acat by slot,          B = g_w2cat, epi -> atomicAdd out)
template <int MODE>
__global__ void __launch_bounds__(256) moe_gemm(float* __restrict__ out) {
    __shared__ __nv_bfloat16 As[2][128][SAS];
    __shared__ __nv_bfloat16 Bs[2][128][SAS];
    __shared__ int   tok_s[128];
    __shared__ float wt_s [128];

    int e = blockIdx.z;
    int cnt = g_count[e];
    int m0 = blockIdx.y * 128;
    if (m0 >= cnt) return;
    int base = g_off[e];
    int n0 = blockIdx.x * 128;

    int tid = threadIdx.x, lane = tid & 31, wid = tid >> 5;
    int wm = wid & 1, wn = wid >> 1;        // warp grid 2 x 4 -> 64 x 32 per warp
    int g = lane >> 2, tig = lane & 3;

    if (tid < 128) {
        int slot = base + m0 + tid; if (slot >= SLOTS) slot = SLOTS - 1;
        tok_s[tid] = g_tok[slot];
        wt_s [tid] = g_wt[slot];
    }
    __syncthreads();

    const __nv_bfloat16* Acat = MODE ? g_acat : g_xcat;
    const __nv_bfloat16* Bexp = (MODE ? g_w2cat : g_w1cat) + (size_t)e * 1024 * K3;

    // global load assignment: 512 uint4 per tile, 2 per thread
    int arow0 = tid >> 2, arow1 = arow0 + 64;
    int aseg  = (tid & 3) * 8;
    size_t Ar0, Ar1;
    if (MODE == 0) {
        Ar0 = (size_t)tok_s[arow0] * K3 + aseg;
        Ar1 = (size_t)tok_s[arow1] * K3 + aseg;
    } else {
        int s0 = base + m0 + arow0; if (s0 >= SLOTS) s0 = SLOTS - 1;
        int s1 = base + m0 + arow1; if (s1 >= SLOTS) s1 = SLOTS - 1;
        Ar0 = (size_t)s0 * K3 + aseg;
        Ar1 = (size_t)s1 * K3 + aseg;
    }
    size_t Br0 = (size_t)(n0 + arow0) * K3 + aseg;
    size_t Br1 = (size_t)(n0 + arow1) * K3 + aseg;

    float acc[4][4][4];
#pragma unroll
    for (int i = 0; i < 4; i++)
#pragma unroll
        for (int j = 0; j < 4; j++)
#pragma unroll
            for (int q = 0; q < 4; q++) acc[i][j][q] = 0.0f;

    // prologue: chunk 0 -> stage 0
    {
        uint4 a0 = *(const uint4*)(Acat + Ar0);
        uint4 a1 = *(const uint4*)(Acat + Ar1);
        uint4 b0 = *(const uint4*)(Bexp + Br0);
        uint4 b1 = *(const uint4*)(Bexp + Br1);
        *(uint4*)&As[0][arow0][aseg] = a0;
        *(uint4*)&As[0][arow1][aseg] = a1;
        *(uint4*)&Bs[0][arow0][aseg] = b0;
        *(uint4*)&Bs[0][arow1][aseg] = b1;
    }
    __syncthreads();

    uint4 pa0, pa1, pb0, pb1;
#pragma unroll 1
    for (int c = 0; c < NCH; c++) {
        int s = c & 1;
        bool pf = (c + 1 < NCH);
        if (pf) {
            size_t kb = (size_t)(c + 1) * BK;
            pa0 = *(const uint4*)(Acat + Ar0 + kb);
            pa1 = *(const uint4*)(Acat + Ar1 + kb);
            pb0 = *(const uint4*)(Bexp + Br0 + kb);
            pb1 = *(const uint4*)(Bexp + Br1 + kb);
        }
#pragma unroll
        for (int ks = 0; ks < 2; ks++) {
            int kc = ks * 16;
            uint32_t af[4][4], bfr[4][2];
#pragma unroll
            for (int mt = 0; mt < 4; mt++) {
                int r = wm * 64 + mt * 16 + g;
                af[mt][0] = *(const uint32_t*)&As[s][r    ][kc + tig * 2];
                af[mt][1] = *(const uint32_t*)&As[s][r + 8][kc + tig * 2];
                af[mt][2] = *(const uint32_t*)&As[s][r    ][kc + tig * 2 + 8];
                af[mt][3] = *(const uint32_t*)&As[s][r + 8][kc + tig * 2 + 8];
            }
#pragma unroll
            for (int nt = 0; nt < 4; nt++) {
                int rb = wn * 32 + nt * 8 + g;
                bfr[nt][0] = *(const uint32_t*)&Bs[s][rb][kc + tig * 2];
                bfr[nt][1] = *(const uint32_t*)&Bs[s][rb][kc + tig * 2 + 8];
            }
#pragma unroll
            for (int mt = 0; mt < 4; mt++)
#pragma unroll
                for (int nt = 0; nt < 4; nt++)
                    mma16816(acc[mt][nt], af[mt], bfr[nt]);
        }
        if (pf) {
            int d = s ^ 1;
            *(uint4*)&As[d][arow0][aseg] = pa0;
            *(uint4*)&As[d][arow1][aseg] = pa1;
            *(uint4*)&Bs[d][arow0][aseg] = pb0;
            *(uint4*)&Bs[d][arow1][aseg] = pb1;
        }
        __syncthreads();
    }

    // ---------------- epilogue ----------------
#pragma unroll
    for (int mt = 0; mt < 4; mt++) {
#pragma unroll
        for (int half = 0; half < 2; half++) {
            int ml = wm * 64 + mt * 16 + g + half * 8;   // local row 0..127
            int m = m0 + ml;
            if (m >= cnt) continue;
            if (MODE == 0) {
                int slot = base + m;
                float wt = wt_s[ml];
                __nv_bfloat16* dst = g_acat + (size_t)slot * K3;
#pragma unroll
                for (int nt = 0; nt < 4; nt++) {
                    int n = n0 + wn * 32 + nt * 8 + tig * 2;
                    float h0 = acc[mt][nt][half * 2 + 0];
                    float h1 = acc[mt][nt][half * 2 + 1];
                    float a0 = (h0 > 0.0f) ? wt * h0 * h0 : 0.0f;
                    float a1 = (h1 > 0.0f) ? wt * h1 * h1 : 0.0f;
                    __nv_bfloat16 hi0 = __float2bfloat16(a0);
                    __nv_bfloat16 hi1 = __float2bfloat16(a1);
                    __nv_bfloat16 lo0 = __float2bfloat16(a0 - __bfloat162float(hi0));
                    __nv_bfloat16 lo1 = __float2bfloat16(a1 - __bfloat162float(hi1));
                    __nv_bfloat162 hh; hh.x = hi0; hh.y = hi1;
                    __nv_bfloat162 ll; ll.x = lo0; ll.y = lo1;
                    *(__nv_bfloat162*)(dst + n)        = hh;
                    *(__nv_bfloat162*)(dst + 1024 + n) = hh;
                    *(__nv_bfloat162*)(dst + 2048 + n) = ll;
                }
            } else {
                int tok = tok_s[ml];
                float* orow = out + (size_t)tok * D_DIM;
#pragma unroll
                for (int nt = 0; nt < 4; nt++) {
                    int n = n0 + wn * 32 + nt * 8 + tig * 2;
                    atomicAdd(&orow[n],     acc[mt][nt][half * 2 + 0]);
                    atomicAdd(&orow[n + 1], acc[mt][nt][half * 2 + 1]);
                }
            }
        }
    }
}

// ---------------- launch ------------------------------------------------------
extern "C" void kernel_launch(void* const* d_in, const int* in_sizes, int n_in,
                              void* d_out, int out_size) {
    const float* x  = (const float*)d_in[0];   // [2,2048,1024]
    const float* rw = (const float*)d_in[1];   // [8,1024]
    const float* w1 = (const float*)d_in[2];   // [1024, 8192]
    const float* w2 = (const float*)d_in[3];   // [8192, 1024]
    float* out = (float*)d_out;

    zero_kernel<<<(T_TOK * D_DIM + 255) / 256, 256>>>(out);
    convert_x<<<(T_TOK * D_DIM + 255) / 256, 256>>>(x);

    dim3 tg(32, 32, E_NUM), tb(32, 8);
    convert_w<<<tg, tb>>>(w1, 0);
    convert_w<<<tg, tb>>>(w2, 1);

    router_kernel<<<(T_TOK * 32 + 255) / 256, 256>>>(x, rw);
    offsets_kernel<<<1, 32>>>();
    fill_kernel<<<(T_TOK + 255) / 256, 256>>>();

    dim3 gup(W_DIM / 128, T_TOK / 128, E_NUM);   // (8, 32, 8)
    moe_gemm<0><<<gup, 256>>>(out);
    dim3 gdn(D_DIM / 128, T_TOK / 128, E_NUM);   // (8, 32, 8)
    moe_gemm<1><<<gdn, 256>>>(out);
}